// round 16
// baseline (speedup 1.0000x reference)
#include <cuda_runtime.h>
#include <cuda_bf16.h>
#include <cstdint>

#define Bb 1024
#define Nn 16
#define Ii 256
#define Hh 1024
#define H3 3072
typedef __nv_bfloat16 bf16;

// ---- fp32 scratch ----
__device__ __align__(256) float g_gie [(size_t)Bb*Nn*H3];   // interleaved gates
__device__ __align__(256) float g_henc[(size_t)Bb*Nn*Hh];
__device__ __align__(256) float g_w1xe[(size_t)Bb*Nn*Hh];
__device__ __align__(256) float g_h   [Bb*Hh];
__device__ __align__(256) float g_heff[Bb*Hh];
__device__ __align__(256) float g_gh  [Bb*H3];               // interleaved gates
__device__ __align__(256) float g_hw2 [Bb*Hh];
__device__ __align__(256) float g_tgate[Nn*Bb];
__device__ __align__(256) float g_pb  [4][H3];               // permuted biases
__device__ __align__(256) int   g_idx  [Nn*Bb];
// ---- bf16 triple-K operand buffers: A'=[hi|lo|hi], B'=[hi|hi|lo] ----
__device__ __align__(256) bf16 g_inA  [(size_t)Bb*Nn*3*Ii];
__device__ __align__(256) bf16 g_hencA[(size_t)Bb*Nn*3*Hh];
__device__ __align__(256) bf16 g_act  [(size_t)Bb*3*Hh];   // split(heff(t)) / enc gated h
__device__ __align__(256) bf16 g_actH [(size_t)Bb*3*Hh];   // split(h(t)) for hW2
__device__ __align__(256) bf16 g_ip   [(size_t)Bb*3*Ii];
__device__ __align__(256) bf16 g_wihe [(size_t)H3*3*Ii];   // rows gate-interleaved
__device__ __align__(256) bf16 g_whhe [(size_t)H3*3*Hh];   // rows gate-interleaved
__device__ __align__(256) bf16 g_wihd [(size_t)H3*3*Ii];   // rows gate-interleaved
__device__ __align__(256) bf16 g_whhd [(size_t)H3*3*Hh];   // rows gate-interleaved
__device__ __align__(256) bf16 g_w1t  [(size_t)Hh*3*Hh];
__device__ __align__(256) bf16 g_w2t  [(size_t)Hh*3*Hh];

// ---- helpers ----
__device__ __forceinline__ float fsig(float x){ return __fdividef(1.0f, 1.0f + __expf(-x)); }
__device__ __forceinline__ float ftanh(float x){ return 1.0f - __fdividef(2.0f, __expf(2.0f*x)+1.0f); }
__device__ __forceinline__ uint32_t s2u(const void* p){
    uint32_t a; asm("{ .reg .u64 t; cvta.to.shared.u64 t, %1; cvt.u32.u64 %0, t; }":"=r"(a):"l"(p)); return a;
}
__device__ __forceinline__ uint32_t swz(uint32_t o){ return o ^ ((o>>3)&0x70); }
__device__ __forceinline__ void cp16(uint32_t s, const void* g){
    asm volatile("cp.async.cg.shared.global [%0], [%1], 16;"::"r"(s),"l"(g));
}
__device__ __forceinline__ void ldsm4(uint32_t& r0,uint32_t& r1,uint32_t& r2,uint32_t& r3,uint32_t a){
    asm volatile("ldmatrix.sync.aligned.m8n8.x4.shared.b16 {%0,%1,%2,%3},[%4];"
        :"=r"(r0),"=r"(r1),"=r"(r2),"=r"(r3):"r"(a));
}
__device__ __forceinline__ void mma16816(float* c,uint32_t a0,uint32_t a1,uint32_t a2,uint32_t a3,uint32_t b0,uint32_t b1){
    asm volatile("mma.sync.aligned.m16n8k16.row.col.f32.bf16.bf16.f32 {%0,%1,%2,%3},{%4,%5,%6,%7},{%8,%9},{%0,%1,%2,%3};"
        :"+f"(c[0]),"+f"(c[1]),"+f"(c[2]),"+f"(c[3])
        :"r"(a0),"r"(a1),"r"(a2),"r"(a3),"r"(b0),"r"(b1));
}
__device__ __forceinline__ void split3(float x, bf16* d, size_t base, int K, int c){
    bf16 h = __float2bfloat16(x);
    bf16 lo = __float2bfloat16(x - __bfloat162float(h));
    d[base+c] = h; d[base+K+c] = lo; d[base+2*K+c] = h;
}

// ---- GEMM core: acc += A'(128,K) @ B'(BN,K)^T tile; 3-stage cp.async ----
template<int BN>
__device__ __forceinline__ void gemm_core(
    const bf16* __restrict__ A, const bf16* __restrict__ B,
    int bm, int bn, int K, char* smem, float (&acc)[2][BN/16][4])
{
    constexpr int WN  = BN/2;
    constexpr int STG = 16384 + BN*128;
    const uint32_t sb = s2u(smem);
    const int tid = threadIdx.x, w = tid>>5, l = tid&31;
    const int wy = w&3, wx = w>>2;
    const int NC = K>>6;
    const bf16* Ag = A + (size_t)bm*K;
    const bf16* Bg = B + (size_t)bn*K;

    auto load = [&](int c){
        uint32_t st = sb + (uint32_t)(c%3)*STG;
        int ko = c<<6;
        #pragma unroll
        for (int i=0;i<4;i++){
            int blk = tid + (i<<8); int row = blk>>3, sg = blk&7;
            uint32_t off = swz((uint32_t)(row*128 + sg*16));
            cp16(st+off, Ag + (size_t)row*K + ko + sg*8);
        }
        #pragma unroll
        for (int i=0;i<BN/32;i++){
            int blk = tid + (i<<8); int row = blk>>3, sg = blk&7;
            uint32_t off = swz((uint32_t)(row*128 + sg*16));
            cp16(st+16384u+off, Bg + (size_t)row*K + ko + sg*8);
        }
        asm volatile("cp.async.commit_group;":::"memory");
    };

    #pragma unroll
    for (int i=0;i<2;i++)
        #pragma unroll
        for (int j=0;j<BN/16;j++)
            #pragma unroll
            for (int q=0;q<4;q++) acc[i][j][q] = 0.f;

    const int lr = l & 15, lg = l >> 4;
    load(0); load(1);
    for (int c=0;c<NC;c++){
        if (c+1<NC) asm volatile("cp.async.wait_group 1;":::"memory");
        else        asm volatile("cp.async.wait_group 0;":::"memory");
        __syncthreads();
        if (c+2<NC) load(c+2);
        uint32_t sA = sb + (uint32_t)(c%3)*STG;
        uint32_t sB = sA + 16384u;
        #pragma unroll
        for (int s=0;s<4;s++){
            uint32_t af[2][4];
            #pragma unroll
            for (int i=0;i<2;i++){
                uint32_t a = sA + swz((uint32_t)((wy*32 + i*16 + lr)*128 + s*32 + lg*16));
                ldsm4(af[i][0],af[i][1],af[i][2],af[i][3], a);
            }
            #pragma unroll
            for (int j=0;j<WN/16;j++){
                uint32_t b0,b1,b2,b3;
                uint32_t a = sB + swz((uint32_t)((wx*WN + j*16 + lr)*128 + s*32 + lg*16));
                ldsm4(b0,b1,b2,b3, a);
                #pragma unroll
                for (int i=0;i<2;i++){
                    mma16816(acc[i][2*j  ], af[i][0],af[i][1],af[i][2],af[i][3], b0,b2);
                    mma16816(acc[i][2*j+1], af[i][0],af[i][1],af[i][2],af[i][3], b1,b3);
                }
            }
        }
    }
}

// plain GEMM: epilogue to gmem
template<int BN>
__device__ __forceinline__ void gemm_body(
    const bf16* __restrict__ A, const bf16* __restrict__ B,
    const float* __restrict__ bias, float* __restrict__ C,
    int bm, int bn, int N, int K, char* smem)
{
    float acc[2][BN/16][4];
    gemm_core<BN>(A, B, bm, bn, K, smem, acc);
    const int tid = threadIdx.x, w = tid>>5, l = tid&31;
    const int wy = w&3, wx = w>>2;
    #pragma unroll
    for (int i=0;i<2;i++){
        int row0 = bm + wy*32 + i*16 + (l>>2);
        #pragma unroll
        for (int j=0;j<BN/16;j++){
            int col = bn + wx*(BN/2) + j*8 + (l&3)*2;
            float bx=0.f, by=0.f;
            if (bias){ bx = bias[col]; by = bias[col+1]; }
            float2 v0 = make_float2(acc[i][j][0]+bx, acc[i][j][1]+by);
            float2 v1 = make_float2(acc[i][j][2]+bx, acc[i][j][3]+by);
            *reinterpret_cast<float2*>(C + (size_t)row0*N + col)     = v0;
            *reinterpret_cast<float2*>(C + (size_t)(row0+8)*N + col) = v1;
        }
    }
}

template<int BN>
__global__ void __launch_bounds__(256, 2)
mgemm(const bf16* __restrict__ A, const bf16* __restrict__ B,
      const float* __restrict__ bias, float* __restrict__ C, int N, int K)
{
    extern __shared__ char smem[];
    gemm_body<BN>(A, B, bias, C, blockIdx.y<<7, blockIdx.x*BN, N, K, smem);
}

// fused GEMM + GRU combine (gate-interleaved layout). BN=96 -> 32 h-units/CTA.
// ENC: gates = act@whhe^T + pbhh_e; gi slice from g_gie; writes h, henc, act(t+1)
// DEC: gates = ip@wihd^T + pbih_d;  gh from g_gh;       writes h, actH, heff/act(t+1)
template<bool ENC>
__global__ void __launch_bounds__(256, 2)
mgemm_gru(const bf16* __restrict__ A, const bf16* __restrict__ Bw,
          const float* __restrict__ pbias, int K, int t)
{
    extern __shared__ char smem[];
    float acc[2][6][4];
    const int bm = blockIdx.y<<7, bn = blockIdx.x*96;
    gemm_core<96>(A, Bw, bm, bn, K, smem, acc);
    __syncthreads();                      // all warps done with pipeline smem
    float* sgh = (float*)smem;            // [128][100] staged gate tile
    const int tid = threadIdx.x, w = tid>>5, l = tid&31;
    const int wy = w&3, wx = w>>2;
    #pragma unroll
    for (int i=0;i<2;i++){
        int r0 = wy*32 + i*16 + (l>>2);
        #pragma unroll
        for (int j=0;j<6;j++){
            int c = wx*48 + j*8 + (l&3)*2;
            sgh[r0*100 + c]      = acc[i][j][0] + pbias[bn+c];
            sgh[r0*100 + c+1]    = acc[i][j][1] + pbias[bn+c+1];
            sgh[(r0+8)*100 + c]  = acc[i][j][2] + pbias[bn+c];
            sgh[(r0+8)*100 + c+1]= acc[i][j][3] + pbias[bn+c+1];
        }
    }
    __syncthreads();
    const int u0 = bn/3;                  // 96 = 3*32 -> exact
    #pragma unroll
    for (int k2=0;k2<16;k2++){
        int item = tid + (k2<<8);
        int row = item >> 5, ul = item & 31;
        int b = bm + row, u = u0 + ul;
        float x0 = sgh[row*100 + 3*ul];
        float x1 = sgh[row*100 + 3*ul+1];
        float x2 = sgh[row*100 + 3*ul+2];
        if (ENC){
            const float* gi = g_gie + (size_t)(b*Nn+t)*H3 + bn;
            float tg = g_tgate[t*Bb+b];
            float hg = tg * g_h[b*Hh+u];
            float r = fsig(gi[3*ul]   + x0);
            float z = fsig(gi[3*ul+1] + x1);
            float g = ftanh(gi[3*ul+2] + r*x2);
            float hn = (1.f-z)*g + z*hg;
            g_h[b*Hh+u] = hn;
            g_henc[(size_t)(b*Nn+t)*Hh+u] = hn;
            if (t < Nn-1) split3(g_tgate[(t+1)*Bb+b]*hn, g_act, (size_t)b*3*Hh, Hh, u);
        } else {
            const float* gh = g_gh + (size_t)b*H3 + bn;
            float r = fsig(x0 + gh[3*ul]);
            float z = fsig(x1 + gh[3*ul+1]);
            float g = ftanh(x2 + r*gh[3*ul+2]);
            float hn = (1.f-z)*g + z*g_heff[b*Hh+u];
            g_h[b*Hh+u] = hn;
            split3(hn, g_actH, (size_t)b*3*Hh, Hh, u);
            if (t < Nn-1){
                float tg = g_tgate[(t+1)*Bb+b];
                float ih = g_henc[(size_t)(b*Nn+g_idx[(t+1)*Bb+b])*Hh+u];
                float he = tg*hn + (1.f-tg)*ih;
                g_heff[b*Hh+u] = he;
                split3(he, g_act, (size_t)b*3*Hh, Hh, u);
            }
        }
    }
}

// decoder pair: id<256 gh(t) interleaved (BN=96); id>=256 hw2(t-1) (BN=64)
__global__ void __launch_bounds__(256, 2)
mgemm_pair(const bf16* __restrict__ act, const bf16* __restrict__ whhd,
           const float* __restrict__ pbhh, float* __restrict__ Cgh,
           const bf16* __restrict__ actH, const bf16* __restrict__ w2t,
           float* __restrict__ Chw2)
{
    extern __shared__ char smem[];
    int id = blockIdx.x;
    if (id < 256)
        gemm_body<96>(act, whhd, pbhh, Cgh, (id>>5)<<7, (id&31)*96, H3, 3*Hh, smem);
    else {
        id -= 256;
        gemm_body<64>(actH, w2t, nullptr, Chw2, (id>>4)<<7, (id&15)<<6, Hh, 3*Hh, smem);
    }
}

// ---- split kernels ----
__global__ void splitA(const float* __restrict__ s, bf16* __restrict__ d, int ksh){
    int i = blockIdx.x*256 + threadIdx.x;
    int K = 1<<ksh, r = i>>ksh, c = i&(K-1);
    float x = s[i];
    bf16 h = __float2bfloat16(x);
    bf16 lo = __float2bfloat16(x - __bfloat162float(h));
    size_t base = (size_t)r*3*K + c;
    d[base] = h; d[base+K] = lo; d[base+2*K] = h;
}
// B-side split; perm=1: gate-interleave rows (r -> 3*(r%1024)+(r/1024))
__global__ void splitB(const float* __restrict__ s, bf16* __restrict__ d, int ksh, int perm){
    int i = blockIdx.x*256 + threadIdx.x;
    int K = 1<<ksh, r = i>>ksh, c = i&(K-1);
    if (perm) r = 3*(r & 1023) + (r >> 10);
    float x = s[i];
    bf16 h = __float2bfloat16(x);
    bf16 lo = __float2bfloat16(x - __bfloat162float(h));
    size_t base = (size_t)r*3*K + c;
    d[base] = h; d[base+K] = h; d[base+2*K] = lo;
}
__global__ void tsplitB(const float* __restrict__ W, bf16* __restrict__ d){
    __shared__ float t[32][33];
    int bx = blockIdx.x<<5, by = blockIdx.y<<5, x = threadIdx.x, y = threadIdx.y;
    #pragma unroll
    for (int j=0;j<32;j+=8) t[y+j][x] = W[(size_t)(by+y+j)*Hh + bx+x];
    __syncthreads();
    #pragma unroll
    for (int j=0;j<32;j+=8){
        float v = t[x][y+j];
        bf16 h = __float2bfloat16(v);
        bf16 lo = __float2bfloat16(v - __bfloat162float(h));
        size_t base = (size_t)(bx+y+j)*3*Hh + (by+x);
        d[base] = h; d[base+Hh] = h; d[base+2*Hh] = lo;
    }
}

// ---- small kernels ----
// setup: tgate/idx + permute all 4 biases
__global__ void setup_kernel(const float* __restrict__ phis,
                             const float* __restrict__ b0, const float* __restrict__ b1,
                             const float* __restrict__ b2, const float* __restrict__ b3){
    int id = blockIdx.x*256 + threadIdx.x; if (id >= Bb*Nn) return;
    if (id < 4*H3){
        int which = id / H3, r = id % H3;
        const float* src = which==0?b0 : which==1?b1 : which==2?b2 : b3;
        g_pb[which][3*(r & 1023) + (r >> 10)] = src[r];
    }
    int b = id>>4, n = id&15;
    const float* prow = phis + (size_t)(b*Nn+n)*Nn;
    float s=0.f;
    #pragma unroll
    for (int k=0;k<Nn;k++) s += prow[k];
    int ns = (int)(s+0.5f);
    g_tgate[n*Bb+b] = (n==0)?1.0f:prow[n-1];
    g_idx[n*Bb+b] = (ns+n-1)&(Nn-1);
}
// encoder t=0: h(0)=0 so gh = pbhh_e; gi interleaved
__global__ void enc0(){
    int id = blockIdx.x*256+threadIdx.x; int b=id>>10, u=id&1023;
    const float* gi = g_gie + (size_t)(b*Nn)*H3;
    const float* pb = g_pb[1];
    float r = fsig(gi[3*u]   + pb[3*u]);
    float z = fsig(gi[3*u+1] + pb[3*u+1]);
    float g = ftanh(gi[3*u+2] + r*pb[3*u+2]);
    float hn = (1.f-z)*g;
    g_h[id] = hn;
    g_henc[(size_t)(b*Nn)*Hh+u] = hn;
    split3(g_tgate[Bb+b]*hn, g_act, (size_t)b*3*Hh, Hh, u);
}
__global__ void dec_init(const float* __restrict__ it){
    int id = blockIdx.x*256+threadIdx.x; int b=id>>10, h=id&1023;
    float h0 = g_henc[(size_t)(b*Nn+g_idx[b])*Hh+h];
    g_h[id] = h0; g_heff[id] = h0;
    split3(h0, g_act, (size_t)b*3*Hh, Hh, h);
    if (h<Ii) split3(it[h], g_ip, (size_t)b*3*Ii, Ii, h);
}
// fused: u logits + masked softmax + context matvec + gated ip(t+1) split
__global__ void attn_fused(const float* __restrict__ v, const float* __restrict__ phis,
                           const float* __restrict__ input, const float* __restrict__ it,
                           float* __restrict__ out, int t, int write_ip){
    __shared__ float su[Nn];
    __shared__ float sat[Nn];
    int b = blockIdx.x, tid = threadIdx.x, w = tid>>5, l = tid&31;
    const float4* hrow = reinterpret_cast<const float4*>(g_hw2 + (size_t)b*Hh);
    const float4* vv4  = reinterpret_cast<const float4*>(v);
    #pragma unroll
    for (int nn=0; nn<2; nn++){
        int n = w + nn*8;
        const float4* wrow = reinterpret_cast<const float4*>(g_w1xe + (size_t)(b*Nn+n)*Hh);
        float s = 0.f;
        #pragma unroll
        for (int i=l; i<256; i+=32){
            float4 a = wrow[i], h4 = hrow[i], vv = vv4[i];
            s += ftanh(a.x+h4.x)*vv.x + ftanh(a.y+h4.y)*vv.y
               + ftanh(a.z+h4.z)*vv.z + ftanh(a.w+h4.w)*vv.w;
        }
        #pragma unroll
        for (int o=16;o;o>>=1) s += __shfl_xor_sync(0xffffffffu, s, o);
        if (l==0) su[n] = s;
    }
    __syncthreads();
    if (tid<Nn){
        float mask = phis[(size_t)(b*Nn+t)*Nn+tid];
        float um = su[tid]*mask;
        float m = um;
        #pragma unroll
        for (int o=8;o;o>>=1) m = fmaxf(m, __shfl_xor_sync(0xffffu, m, o));
        float e = __expf(um-m)*mask;
        float ss = e;
        #pragma unroll
        for (int o=8;o;o>>=1) ss += __shfl_xor_sync(0xffffu, ss, o);
        float a = e/ss;
        sat[tid]=a;
        out[(size_t)(b*Nn+t)*Nn+tid]=a;
    }
    __syncthreads();
    if (write_ip){
        float s = 0.f;
        const float* irow = input + (size_t)b*Nn*Ii + tid;
        #pragma unroll
        for (int n=0;n<Nn;n++) s += sat[n]*irow[n*Ii];
        float tg = g_tgate[(t+1)*Bb+b];
        float ni = tg*s + (1.0f-tg)*it[tid];
        split3(ni, g_ip, (size_t)b*3*Ii, Ii, tid);
    }
}

// ---- driver ----
#define SYM(p,s) cudaGetSymbolAddress((void**)&p, s)
extern "C" void kernel_launch(void* const* d_in, const int* in_sizes, int n_in,
                              void* d_out, int out_size){
    const float* input=(const float*)d_in[0];  const float* phis =(const float*)d_in[1];
    const float* itok =(const float*)d_in[2];  const float* W1   =(const float*)d_in[3];
    const float* W2   =(const float*)d_in[4];  const float* v    =(const float*)d_in[5];
    const float* Wih_e=(const float*)d_in[6];  const float* Whh_e=(const float*)d_in[7];
    const float* bih_e=(const float*)d_in[8];  const float* bhh_e=(const float*)d_in[9];
    const float* Wih_d=(const float*)d_in[10]; const float* Whh_d=(const float*)d_in[11];
    const float* bih_d=(const float*)d_in[12]; const float* bhh_d=(const float*)d_in[13];
    float* out=(float*)d_out;

    float *p_gie,*p_henc,*p_w1xe,*p_gh,*p_hw2,*p_pb;
    SYM(p_gie,g_gie); SYM(p_henc,g_henc); SYM(p_w1xe,g_w1xe);
    SYM(p_gh,g_gh); SYM(p_hw2,g_hw2); SYM(p_pb,g_pb);
    bf16 *inA,*hencA,*act,*actH,*ip,*wihe,*whhe,*wihd,*whhd,*w1t,*w2t;
    SYM(inA,g_inA); SYM(hencA,g_hencA); SYM(act,g_act); SYM(actH,g_actH); SYM(ip,g_ip);
    SYM(wihe,g_wihe); SYM(whhe,g_whhe); SYM(wihd,g_wihd); SYM(whhd,g_whhd);
    SYM(w1t,g_w1t); SYM(w2t,g_w2t);
    const float *pb0 = p_pb, *pb1 = p_pb+H3, *pb2 = p_pb+2*H3, *pb3 = p_pb+3*H3;

    const int SM128 = 3*(16384 + 128*128);   // 98304
    const int SM96  = 3*(16384 + 96*128);    // 86016 (>= 128*100*4 staging)
    const int SM64  = 3*(16384 + 64*128);    // 73728
    cudaFuncSetAttribute((void*)mgemm<128>, cudaFuncAttributeMaxDynamicSharedMemorySize, SM128);
    cudaFuncSetAttribute((void*)mgemm<96>,  cudaFuncAttributeMaxDynamicSharedMemorySize, SM96);
    cudaFuncSetAttribute((void*)mgemm<64>,  cudaFuncAttributeMaxDynamicSharedMemorySize, SM64);
    cudaFuncSetAttribute((void*)mgemm_pair, cudaFuncAttributeMaxDynamicSharedMemorySize, SM96);
    cudaFuncSetAttribute((void*)mgemm_gru<true>,  cudaFuncAttributeMaxDynamicSharedMemorySize, SM96);
    cudaFuncSetAttribute((void*)mgemm_gru<false>, cudaFuncAttributeMaxDynamicSharedMemorySize, SM96);
    const int EW = (Bb*Hh)/256;

    // prologue (4th launch = big mgemm, for ncu -s targeting)
    setup_kernel<<<(Bb*Nn+255)/256,256>>>(phis, bih_e, bhh_e, bih_d, bhh_d);  // 1
    splitB<<<(H3*Ii)/256,256>>>(Wih_e, wihe, 8, 1);                            // 2
    splitA<<<(Bb*Nn*Ii)/256,256>>>(input, inA, 8);                             // 3
    mgemm<128><<<dim3(H3/128,(Bb*Nn)/128),256,SM128>>>(                        // 4 <- profiled
        inA, wihe, pb0, p_gie, H3, 3*Ii);
    splitB<<<(H3*Hh)/256,256>>>(Whh_e, whhe, 10, 1);
    splitB<<<(H3*Ii)/256,256>>>(Wih_d, wihd, 8, 1);
    splitB<<<(H3*Hh)/256,256>>>(Whh_d, whhd, 10, 1);
    tsplitB<<<dim3(32,32),dim3(32,8)>>>(W1, w1t);
    tsplitB<<<dim3(32,32),dim3(32,8)>>>(W2, w2t);

    // encoder: t=0 closed-form; t>=1 fused GEMM+GRU (one launch/step)
    enc0<<<EW,256>>>();
    for (int t=1;t<Nn;t++)
        mgemm_gru<true><<<dim3(32,8),256,SM96>>>(act, whhe, pb1, 3*Hh, t);

    // W1xe = henc @ W1
    splitA<<<(Bb*Nn*Hh)/256,256>>>(p_henc, hencA, 10);
    mgemm<128><<<dim3(Hh/128,(Bb*Nn)/128),256,SM128>>>(hencA, w1t, nullptr, p_w1xe, Hh, 3*Hh);

    dec_init<<<EW,256>>>(itok);
    // decoder: pair(gh+hw2) -> attn -> fused gi_d GEMM + GRU
    for (int t=0;t<Nn;t++){
        if (t==0)
            mgemm<96><<<dim3(H3/96,Bb/128),256,SM96>>>(act, whhd, pb3, p_gh, H3, 3*Hh);
        else {
            mgemm_pair<<<384,256,SM96>>>(act, whhd, pb3, p_gh, actH, w2t, p_hw2);
            attn_fused<<<Bb,256>>>(v, phis, input, itok, out, t-1, 1);
        }
        mgemm_gru<false><<<dim3(32,8),256,SM96>>>(ip, wihd, pb2, 3*Ii, t);
    }
    mgemm<64><<<dim3(Hh/64,Bb/128),256,SM64>>>(actH, w2t, nullptr, p_hw2, Hh, 3*Hh);
    attn_fused<<<Bb,256>>>(v, phis, input, itok, out, Nn-1, 0);
}

// round 17
// speedup vs baseline: 1.0865x; 1.0865x over previous
#include <cuda_runtime.h>
#include <cuda_bf16.h>
#include <cstdint>

#define Bb 1024
#define Nn 16
#define Ii 256
#define Hh 1024
#define H3 3072
typedef __nv_bfloat16 bf16;

// ---- fp32 scratch ----
__device__ __align__(256) float g_gie [(size_t)Bb*Nn*H3];
__device__ __align__(256) float g_henc[(size_t)Bb*Nn*Hh];
__device__ __align__(256) float g_w1xe[(size_t)Bb*Nn*Hh];
__device__ __align__(256) float g_h   [Bb*Hh];
__device__ __align__(256) float g_heff[Bb*Hh];
__device__ __align__(256) float g_gh  [Bb*H3];
__device__ __align__(256) float g_gid [Bb*H3];
__device__ __align__(256) float g_hw2 [Bb*Hh];
__device__ __align__(256) float g_tgate[Nn*Bb];
__device__ __align__(256) int   g_idx  [Nn*Bb];
// ---- bf16 triple-K operand buffers: A'=[hi|lo|hi], B'=[hi|hi|lo] ----
__device__ __align__(256) bf16 g_inA  [(size_t)Bb*Nn*3*Ii];
__device__ __align__(256) bf16 g_hencA[(size_t)Bb*Nn*3*Hh];
__device__ __align__(256) bf16 g_act  [(size_t)Bb*3*Hh];   // split(heff(t)) / enc gated h
__device__ __align__(256) bf16 g_actH [(size_t)Bb*3*Hh];   // split(h(t)) for hW2
__device__ __align__(256) bf16 g_ip   [(size_t)Bb*3*Ii];
__device__ __align__(256) bf16 g_wihe [(size_t)H3*3*Ii];
__device__ __align__(256) bf16 g_whhe [(size_t)H3*3*Hh];
__device__ __align__(256) bf16 g_wihd [(size_t)H3*3*Ii];
__device__ __align__(256) bf16 g_whhd [(size_t)H3*3*Hh];
__device__ __align__(256) bf16 g_w1t  [(size_t)Hh*3*Hh];
__device__ __align__(256) bf16 g_w2t  [(size_t)Hh*3*Hh];

// ---- helpers ----
__device__ __forceinline__ float fsig(float x){ return __fdividef(1.0f, 1.0f + __expf(-x)); }
__device__ __forceinline__ float ftanh(float x){ return 1.0f - __fdividef(2.0f, __expf(2.0f*x)+1.0f); }
__device__ __forceinline__ uint32_t s2u(const void* p){
    uint32_t a; asm("{ .reg .u64 t; cvta.to.shared.u64 t, %1; cvt.u32.u64 %0, t; }":"=r"(a):"l"(p)); return a;
}
__device__ __forceinline__ uint32_t swz(uint32_t o){ return o ^ ((o>>3)&0x70); }
__device__ __forceinline__ void cp16(uint32_t s, const void* g){
    asm volatile("cp.async.cg.shared.global [%0], [%1], 16;"::"r"(s),"l"(g));
}
__device__ __forceinline__ void ldsm4(uint32_t& r0,uint32_t& r1,uint32_t& r2,uint32_t& r3,uint32_t a){
    asm volatile("ldmatrix.sync.aligned.m8n8.x4.shared.b16 {%0,%1,%2,%3},[%4];"
        :"=r"(r0),"=r"(r1),"=r"(r2),"=r"(r3):"r"(a));
}
__device__ __forceinline__ void mma16816(float* c,uint32_t a0,uint32_t a1,uint32_t a2,uint32_t a3,uint32_t b0,uint32_t b1){
    asm volatile("mma.sync.aligned.m16n8k16.row.col.f32.bf16.bf16.f32 {%0,%1,%2,%3},{%4,%5,%6,%7},{%8,%9},{%0,%1,%2,%3};"
        :"+f"(c[0]),"+f"(c[1]),"+f"(c[2]),"+f"(c[3])
        :"r"(a0),"r"(a1),"r"(a2),"r"(a3),"r"(b0),"r"(b1));
}
// scalar split (attn kernel)
__device__ __forceinline__ void split3(float x, bf16* d, size_t base, int K, int c){
    bf16 h = __float2bfloat16(x);
    bf16 lo = __float2bfloat16(x - __bfloat162float(h));
    d[base+c] = h; d[base+K+c] = lo; d[base+2*K+c] = h;
}
// vector split helpers (identical rounding to scalar path)
__device__ __forceinline__ float lo_of(float x){ return x - __bfloat162float(__float2bfloat16(x)); }
__device__ __forceinline__ void st4h(bf16* p, float4 v){
    ((__nv_bfloat162*)p)[0] = __floats2bfloat162_rn(v.x, v.y);
    ((__nv_bfloat162*)p)[1] = __floats2bfloat162_rn(v.z, v.w);
}
__device__ __forceinline__ void st4l(bf16* p, float4 v){
    ((__nv_bfloat162*)p)[0] = __floats2bfloat162_rn(lo_of(v.x), lo_of(v.y));
    ((__nv_bfloat162*)p)[1] = __floats2bfloat162_rn(lo_of(v.z), lo_of(v.w));
}
__device__ __forceinline__ void split3v(float4 v, bf16* d, size_t base, int K, int c){
    st4h(d+base+c, v); st4l(d+base+K+c, v); st4h(d+base+2*K+c, v);
}
__device__ __forceinline__ float gru1(float ir,float iz,float ig,float hr,float hz,float hg,float hold){
    float r=fsig(ir+hr), z=fsig(iz+hz), g=ftanh(ig+r*hg);
    return (1.f-z)*g + z*hold;
}

// ---- GEMM core (identical to R15) ----
template<int BN>
__device__ __forceinline__ void gemm_core(
    const bf16* __restrict__ A, const bf16* __restrict__ B,
    int bm, int bn, int K, char* smem, float (&acc)[2][BN/16][4])
{
    constexpr int WN  = BN/2;
    constexpr int STG = 16384 + BN*128;
    const uint32_t sb = s2u(smem);
    const int tid = threadIdx.x, w = tid>>5, l = tid&31;
    const int wy = w&3, wx = w>>2;
    const int NC = K>>6;
    const bf16* Ag = A + (size_t)bm*K;
    const bf16* Bg = B + (size_t)bn*K;

    auto load = [&](int c){
        uint32_t st = sb + (uint32_t)(c%3)*STG;
        int ko = c<<6;
        #pragma unroll
        for (int i=0;i<4;i++){
            int blk = tid + (i<<8); int row = blk>>3, sg = blk&7;
            uint32_t off = swz((uint32_t)(row*128 + sg*16));
            cp16(st+off, Ag + (size_t)row*K + ko + sg*8);
        }
        #pragma unroll
        for (int i=0;i<BN/32;i++){
            int blk = tid + (i<<8); int row = blk>>3, sg = blk&7;
            uint32_t off = swz((uint32_t)(row*128 + sg*16));
            cp16(st+16384u+off, Bg + (size_t)row*K + ko + sg*8);
        }
        asm volatile("cp.async.commit_group;":::"memory");
    };

    #pragma unroll
    for (int i=0;i<2;i++)
        #pragma unroll
        for (int j=0;j<BN/16;j++)
            #pragma unroll
            for (int q=0;q<4;q++) acc[i][j][q] = 0.f;

    const int lr = l & 15, lg = l >> 4;
    load(0); load(1);
    for (int c=0;c<NC;c++){
        if (c+1<NC) asm volatile("cp.async.wait_group 1;":::"memory");
        else        asm volatile("cp.async.wait_group 0;":::"memory");
        __syncthreads();
        if (c+2<NC) load(c+2);
        uint32_t sA = sb + (uint32_t)(c%3)*STG;
        uint32_t sB = sA + 16384u;
        #pragma unroll
        for (int s=0;s<4;s++){
            uint32_t af[2][4];
            #pragma unroll
            for (int i=0;i<2;i++){
                uint32_t a = sA + swz((uint32_t)((wy*32 + i*16 + lr)*128 + s*32 + lg*16));
                ldsm4(af[i][0],af[i][1],af[i][2],af[i][3], a);
            }
            #pragma unroll
            for (int j=0;j<WN/16;j++){
                uint32_t b0,b1,b2,b3;
                uint32_t a = sB + swz((uint32_t)((wx*WN + j*16 + lr)*128 + s*32 + lg*16));
                ldsm4(b0,b1,b2,b3, a);
                #pragma unroll
                for (int i=0;i<2;i++){
                    mma16816(acc[i][2*j  ], af[i][0],af[i][1],af[i][2],af[i][3], b0,b2);
                    mma16816(acc[i][2*j+1], af[i][0],af[i][1],af[i][2],af[i][3], b1,b3);
                }
            }
        }
    }
}

template<int BN>
__device__ __forceinline__ void gemm_body(
    const bf16* __restrict__ A, const bf16* __restrict__ B,
    const float* __restrict__ bias, float* __restrict__ C,
    int bm, int bn, int N, int K, char* smem)
{
    float acc[2][BN/16][4];
    gemm_core<BN>(A, B, bm, bn, K, smem, acc);
    const int tid = threadIdx.x, w = tid>>5, l = tid&31;
    const int wy = w&3, wx = w>>2;
    #pragma unroll
    for (int i=0;i<2;i++){
        int row0 = bm + wy*32 + i*16 + (l>>2);
        #pragma unroll
        for (int j=0;j<BN/16;j++){
            int col = bn + wx*(BN/2) + j*8 + (l&3)*2;
            float bx=0.f, by=0.f;
            if (bias){ bx = bias[col]; by = bias[col+1]; }
            float2 v0 = make_float2(acc[i][j][0]+bx, acc[i][j][1]+by);
            float2 v1 = make_float2(acc[i][j][2]+bx, acc[i][j][3]+by);
            *reinterpret_cast<float2*>(C + (size_t)row0*N + col)     = v0;
            *reinterpret_cast<float2*>(C + (size_t)(row0+8)*N + col) = v1;
        }
    }
}

template<int BN>
__global__ void __launch_bounds__(256, 2)
mgemm(const bf16* __restrict__ A, const bf16* __restrict__ B,
      const float* __restrict__ bias, float* __restrict__ C, int N, int K)
{
    extern __shared__ char smem[];
    gemm_body<BN>(A, B, bias, C, blockIdx.y<<7, blockIdx.x*BN, N, K, smem);
}

// decoder pair (t>=1): id<256 gh(t) BN96; id>=256 hw2(t-1) BN64
__global__ void __launch_bounds__(256, 2)
mgemm_pair(const bf16* __restrict__ act, const bf16* __restrict__ whhd,
           const float* __restrict__ bhh, float* __restrict__ Cgh,
           const bf16* __restrict__ actH, const bf16* __restrict__ w2t,
           float* __restrict__ Chw2)
{
    extern __shared__ char smem[];
    int id = blockIdx.x;
    if (id < 256)
        gemm_body<96>(act, whhd, bhh, Cgh, (id>>5)<<7, (id&31)*96, H3, 3*Hh, smem);
    else {
        id -= 256;
        gemm_body<64>(actH, w2t, nullptr, Chw2, (id>>4)<<7, (id&15)<<6, Hh, 3*Hh, smem);
    }
}

// decoder t=0: gh(0) + gi_d(0) batched (both depend only on dec_init)
__global__ void __launch_bounds__(256, 2)
mgemm_pair0(const bf16* __restrict__ act, const bf16* __restrict__ whhd,
            const float* __restrict__ bhh, float* __restrict__ Cgh,
            const bf16* __restrict__ ip, const bf16* __restrict__ wihd,
            const float* __restrict__ bih, float* __restrict__ Cgi)
{
    extern __shared__ char smem[];
    int id = blockIdx.x;
    if (id < 256)
        gemm_body<96>(act, whhd, bhh, Cgh, (id>>5)<<7, (id&31)*96, H3, 3*Hh, smem);
    else {
        id -= 256;
        gemm_body<96>(ip, wihd, bih, Cgi, (id>>5)<<7, (id&31)*96, H3, 3*Ii, smem);
    }
}

// ---- split kernels (float4 vectorized) ----
__global__ void splitA(const float* __restrict__ s, bf16* __restrict__ d, int ksh){
    int i4 = (blockIdx.x*256 + threadIdx.x) << 2;
    int K = 1<<ksh, r = i4>>ksh, c = i4&(K-1);
    float4 x = *reinterpret_cast<const float4*>(s+i4);
    size_t base = (size_t)r*3*K;
    st4h(d+base+c, x); st4l(d+base+K+c, x); st4h(d+base+2*K+c, x);
}
__global__ void splitB(const float* __restrict__ s, bf16* __restrict__ d, int ksh){
    int i4 = (blockIdx.x*256 + threadIdx.x) << 2;
    int K = 1<<ksh, r = i4>>ksh, c = i4&(K-1);
    float4 x = *reinterpret_cast<const float4*>(s+i4);
    size_t base = (size_t)r*3*K;
    st4h(d+base+c, x); st4h(d+base+K+c, x); st4l(d+base+2*K+c, x);
}
__global__ void tsplitB(const float* __restrict__ W, bf16* __restrict__ d){
    __shared__ float t[32][33];
    int bx = blockIdx.x<<5, by = blockIdx.y<<5, x = threadIdx.x, y = threadIdx.y;
    #pragma unroll
    for (int j=0;j<32;j+=8) t[y+j][x] = W[(size_t)(by+y+j)*Hh + bx+x];
    __syncthreads();
    #pragma unroll
    for (int j=0;j<32;j+=8){
        float v = t[x][y+j];
        bf16 h = __float2bfloat16(v);
        bf16 lo = __float2bfloat16(v - __bfloat162float(h));
        size_t base = (size_t)(bx+y+j)*3*Hh + (by+x);
        d[base] = h; d[base+Hh] = h; d[base+2*Hh] = lo;
    }
}

// ---- small kernels ----
__global__ void setup_kernel(const float* __restrict__ phis){
    int id = blockIdx.x*256 + threadIdx.x; if (id >= Bb*Nn) return;
    int b = id>>4, n = id&15;
    const float* prow = phis + (size_t)(b*Nn+n)*Nn;
    float s=0.f;
    #pragma unroll
    for (int k=0;k<Nn;k++) s += prow[k];
    int ns = (int)(s+0.5f);
    g_tgate[n*Bb+b] = (n==0)?1.0f:prow[n-1];
    g_idx[n*Bb+b] = (ns+n-1)&(Nn-1);
}
__global__ void zero_init(){
    int i = blockIdx.x*256+threadIdx.x;           // (Bb*Hh/4) threads
    *reinterpret_cast<float4*>(g_h + 4*i) = make_float4(0.f,0.f,0.f,0.f);
}
// GRU combine (vectorized, 4 h/thread); first=1 -> gh = bhh (h(0)=0)
__global__ void enc_combine(int t, const float* __restrict__ bhh, int first){
    int id = blockIdx.x*256+threadIdx.x;          // Bb*256 threads
    int b = id>>8, h4 = (id&255)<<2;
    const float* gi = g_gie + (size_t)(b*Nn+t)*H3;
    float4 ir = *reinterpret_cast<const float4*>(gi+h4);
    float4 iz = *reinterpret_cast<const float4*>(gi+Hh+h4);
    float4 ig = *reinterpret_cast<const float4*>(gi+2*Hh+h4);
    float4 hr,hz,hg;
    if (first){
        hr = *reinterpret_cast<const float4*>(bhh+h4);
        hz = *reinterpret_cast<const float4*>(bhh+Hh+h4);
        hg = *reinterpret_cast<const float4*>(bhh+2*Hh+h4);
    } else {
        const float* gh = g_gh + (size_t)b*H3;
        hr = *reinterpret_cast<const float4*>(gh+h4);
        hz = *reinterpret_cast<const float4*>(gh+Hh+h4);
        hg = *reinterpret_cast<const float4*>(gh+2*Hh+h4);
    }
    float tg = g_tgate[t*Bb+b];
    float4 hold = *reinterpret_cast<const float4*>(g_h + b*Hh + h4);
    float4 hn;
    hn.x = gru1(ir.x,iz.x,ig.x,hr.x,hz.x,hg.x, tg*hold.x);
    hn.y = gru1(ir.y,iz.y,ig.y,hr.y,hz.y,hg.y, tg*hold.y);
    hn.z = gru1(ir.z,iz.z,ig.z,hr.z,hz.z,hg.z, tg*hold.z);
    hn.w = gru1(ir.w,iz.w,ig.w,hr.w,hz.w,hg.w, tg*hold.w);
    *reinterpret_cast<float4*>(g_h + b*Hh + h4) = hn;
    *reinterpret_cast<float4*>(g_henc + (size_t)(b*Nn+t)*Hh + h4) = hn;
    if (t < Nn-1){
        float t2 = g_tgate[(t+1)*Bb+b];
        float4 gv = make_float4(t2*hn.x, t2*hn.y, t2*hn.z, t2*hn.w);
        split3v(gv, g_act, (size_t)b*3*Hh, Hh, h4);
    }
}
__global__ void dec_init(const float* __restrict__ it){
    int id = blockIdx.x*256+threadIdx.x;          // Bb*256
    int b = id>>8, h4 = (id&255)<<2;
    float4 h0 = *reinterpret_cast<const float4*>(g_henc + (size_t)(b*Nn+g_idx[b])*Hh + h4);
    *reinterpret_cast<float4*>(g_h + b*Hh + h4) = h0;
    *reinterpret_cast<float4*>(g_heff + b*Hh + h4) = h0;
    split3v(h0, g_act, (size_t)b*3*Hh, Hh, h4);
    if (h4 < Ii){
        float4 iv = *reinterpret_cast<const float4*>(it + h4);
        split3v(iv, g_ip, (size_t)b*3*Ii, Ii, h4);
    }
}
// GRU combine: h(t); split -> actH; heff(t+1)+split -> act (vectorized)
__global__ void dec_combine(int t){
    int id = blockIdx.x*256+threadIdx.x;          // Bb*256
    int b = id>>8, h4 = (id&255)<<2;
    const float* gi = g_gid + (size_t)b*H3;
    const float* gh = g_gh + (size_t)b*H3;
    float4 ir = *reinterpret_cast<const float4*>(gi+h4);
    float4 iz = *reinterpret_cast<const float4*>(gi+Hh+h4);
    float4 ig = *reinterpret_cast<const float4*>(gi+2*Hh+h4);
    float4 hr = *reinterpret_cast<const float4*>(gh+h4);
    float4 hz = *reinterpret_cast<const float4*>(gh+Hh+h4);
    float4 hg = *reinterpret_cast<const float4*>(gh+2*Hh+h4);
    float4 he = *reinterpret_cast<const float4*>(g_heff + b*Hh + h4);
    float4 hn;
    hn.x = gru1(ir.x,iz.x,ig.x,hr.x,hz.x,hg.x, he.x);
    hn.y = gru1(ir.y,iz.y,ig.y,hr.y,hz.y,hg.y, he.y);
    hn.z = gru1(ir.z,iz.z,ig.z,hr.z,hz.z,hg.z, he.z);
    hn.w = gru1(ir.w,iz.w,ig.w,hr.w,hz.w,hg.w, he.w);
    *reinterpret_cast<float4*>(g_h + b*Hh + h4) = hn;
    split3v(hn, g_actH, (size_t)b*3*Hh, Hh, h4);
    if (t < Nn-1){
        float tg = g_tgate[(t+1)*Bb+b];
        float4 ih = *reinterpret_cast<const float4*>(g_henc + (size_t)(b*Nn+g_idx[(t+1)*Bb+b])*Hh + h4);
        float4 h2 = make_float4(tg*hn.x+(1.f-tg)*ih.x, tg*hn.y+(1.f-tg)*ih.y,
                                tg*hn.z+(1.f-tg)*ih.z, tg*hn.w+(1.f-tg)*ih.w);
        *reinterpret_cast<float4*>(g_heff + b*Hh + h4) = h2;
        split3v(h2, g_act, (size_t)b*3*Hh, Hh, h4);
    }
}
// fused: u logits + masked softmax + context matvec + gated ip(t+1) split
__global__ void attn_fused(const float* __restrict__ v, const float* __restrict__ phis,
                           const float* __restrict__ input, const float* __restrict__ it,
                           float* __restrict__ out, int t, int write_ip){
    __shared__ float su[Nn];
    __shared__ float sat[Nn];
    int b = blockIdx.x, tid = threadIdx.x, w = tid>>5, l = tid&31;
    const float4* hrow = reinterpret_cast<const float4*>(g_hw2 + (size_t)b*Hh);
    const float4* vv4  = reinterpret_cast<const float4*>(v);
    #pragma unroll
    for (int nn=0; nn<2; nn++){
        int n = w + nn*8;
        const float4* wrow = reinterpret_cast<const float4*>(g_w1xe + (size_t)(b*Nn+n)*Hh);
        float s = 0.f;
        #pragma unroll
        for (int i=l; i<256; i+=32){
            float4 a = wrow[i], h4 = hrow[i], vv = vv4[i];
            s += ftanh(a.x+h4.x)*vv.x + ftanh(a.y+h4.y)*vv.y
               + ftanh(a.z+h4.z)*vv.z + ftanh(a.w+h4.w)*vv.w;
        }
        #pragma unroll
        for (int o=16;o;o>>=1) s += __shfl_xor_sync(0xffffffffu, s, o);
        if (l==0) su[n] = s;
    }
    __syncthreads();
    if (tid<Nn){
        float mask = phis[(size_t)(b*Nn+t)*Nn+tid];
        float um = su[tid]*mask;
        float m = um;
        #pragma unroll
        for (int o=8;o;o>>=1) m = fmaxf(m, __shfl_xor_sync(0xffffu, m, o));
        float e = __expf(um-m)*mask;
        float ss = e;
        #pragma unroll
        for (int o=8;o;o>>=1) ss += __shfl_xor_sync(0xffffu, ss, o);
        float a = e/ss;
        sat[tid]=a;
        out[(size_t)(b*Nn+t)*Nn+tid]=a;
    }
    __syncthreads();
    if (write_ip){
        float s = 0.f;
        const float* irow = input + (size_t)b*Nn*Ii + tid;
        #pragma unroll
        for (int n=0;n<Nn;n++) s += sat[n]*irow[n*Ii];
        float tg = g_tgate[(t+1)*Bb+b];
        float ni = tg*s + (1.0f-tg)*it[tid];
        split3(ni, g_ip, (size_t)b*3*Ii, Ii, tid);
    }
}

// ---- driver ----
#define SYM(p,s) cudaGetSymbolAddress((void**)&p, s)
extern "C" void kernel_launch(void* const* d_in, const int* in_sizes, int n_in,
                              void* d_out, int out_size){
    const float* input=(const float*)d_in[0];  const float* phis =(const float*)d_in[1];
    const float* itok =(const float*)d_in[2];  const float* W1   =(const float*)d_in[3];
    const float* W2   =(const float*)d_in[4];  const float* v    =(const float*)d_in[5];
    const float* Wih_e=(const float*)d_in[6];  const float* Whh_e=(const float*)d_in[7];
    const float* bih_e=(const float*)d_in[8];  const float* bhh_e=(const float*)d_in[9];
    const float* Wih_d=(const float*)d_in[10]; const float* Whh_d=(const float*)d_in[11];
    const float* bih_d=(const float*)d_in[12]; const float* bhh_d=(const float*)d_in[13];
    float* out=(float*)d_out;

    float *p_gie,*p_henc,*p_w1xe,*p_gh,*p_gid,*p_hw2;
    SYM(p_gie,g_gie); SYM(p_henc,g_henc); SYM(p_w1xe,g_w1xe);
    SYM(p_gh,g_gh); SYM(p_gid,g_gid); SYM(p_hw2,g_hw2);
    bf16 *inA,*hencA,*act,*actH,*ip,*wihe,*whhe,*wihd,*whhd,*w1t,*w2t;
    SYM(inA,g_inA); SYM(hencA,g_hencA); SYM(act,g_act); SYM(actH,g_actH); SYM(ip,g_ip);
    SYM(wihe,g_wihe); SYM(whhe,g_whhe); SYM(wihd,g_wihd); SYM(whhd,g_whhd);
    SYM(w1t,g_w1t); SYM(w2t,g_w2t);

    const int SM128 = 3*(16384 + 128*128);
    const int SM96  = 3*(16384 + 96*128);
    const int SM64  = 3*(16384 + 64*128);
    cudaFuncSetAttribute((void*)mgemm<128>, cudaFuncAttributeMaxDynamicSharedMemorySize, SM128);
    cudaFuncSetAttribute((void*)mgemm<96>,  cudaFuncAttributeMaxDynamicSharedMemorySize, SM96);
    cudaFuncSetAttribute((void*)mgemm<64>,  cudaFuncAttributeMaxDynamicSharedMemorySize, SM64);
    cudaFuncSetAttribute((void*)mgemm_pair, cudaFuncAttributeMaxDynamicSharedMemorySize, SM96);
    cudaFuncSetAttribute((void*)mgemm_pair0,cudaFuncAttributeMaxDynamicSharedMemorySize, SM96);
    const int EV = (Bb*Hh/4)/256;                 // 1024 CTAs for vector elementwise

    // prologue (4th launch = big mgemm, for ncu -s targeting)
    setup_kernel<<<(Bb*Nn+255)/256,256>>>(phis);                   // 1
    splitB<<<(H3*Ii/4)/256,256>>>(Wih_e, wihe, 8);                 // 2
    splitA<<<(Bb*Nn*Ii/4)/256,256>>>(input, inA, 8);               // 3
    mgemm<128><<<dim3(H3/128,(Bb*Nn)/128),256,SM128>>>(            // 4 <- profiled
        inA, wihe, bih_e, p_gie, H3, 3*Ii);
    zero_init<<<EV,256>>>();
    splitB<<<(H3*Hh/4)/256,256>>>(Whh_e, whhe, 10);
    splitB<<<(H3*Ii/4)/256,256>>>(Wih_d, wihd, 8);
    splitB<<<(H3*Hh/4)/256,256>>>(Whh_d, whhd, 10);
    tsplitB<<<dim3(32,32),dim3(32,8)>>>(W1, w1t);
    tsplitB<<<dim3(32,32),dim3(32,8)>>>(W2, w2t);

    // encoder (t=0 GEMM skipped; BN=96 -> 256 CTAs)
    enc_combine<<<EV,256>>>(0, bhh_e, 1);
    for (int t=1;t<Nn;t++){
        mgemm<96><<<dim3(H3/96,Bb/128),256,SM96>>>(act, whhe, bhh_e, p_gh, H3, 3*Hh);
        enc_combine<<<EV,256>>>(t, bhh_e, 0);
    }

    // W1xe = henc @ W1
    splitA<<<(Bb*Nn*Hh/4)/256,256>>>(p_henc, hencA, 10);
    mgemm<128><<<dim3(Hh/128,(Bb*Nn)/128),256,SM128>>>(hencA, w1t, nullptr, p_w1xe, Hh, 3*Hh);

    dec_init<<<EV,256>>>(itok);
    // decoder
    for (int t=0;t<Nn;t++){
        if (t==0)
            mgemm_pair0<<<512,256,SM96>>>(act, whhd, bhh_d, p_gh, ip, wihd, bih_d, p_gid);
        else {
            mgemm_pair<<<384,256,SM96>>>(act, whhd, bhh_d, p_gh, actH, w2t, p_hw2);
            attn_fused<<<Bb,256>>>(v, phis, input, itok, out, t-1, 1);
            mgemm<96><<<dim3(H3/96,Bb/128),256,SM96>>>(ip, wihd, bih_d, p_gid, H3, 3*Ii);
        }
        dec_combine<<<EV,256>>>(t);
    }
    mgemm<64><<<dim3(Hh/64,Bb/128),256,SM64>>>(actH, w2t, nullptr, p_hw2, Hh, 3*Hh);
    attn_fused<<<Bb,256>>>(v, phis, input, itok, out, Nn-1, 0);
}